// round 13
// baseline (speedup 1.0000x reference)
#include <cuda_runtime.h>
#include <cstdint>

// Problem constants (B=8, H=16, S=1024, D=64)
#define TB   256      // threads per block
#define BM   16       // query rows per block
#define NC   128      // n-chunk (K cols / V rows staged in smem)
#define SS   1024     // seq len
#define DD   64       // head dim
#define NBH  128      // B*H

static constexpr size_t O_ELEMS = (size_t)NBH * SS * DD;   // 8388608
static constexpr size_t W_ELEMS = (size_t)NBH * SS * SS;   // 134217728

// smem: Ss[BM][SS] (64KB) + Qdup[BM][DD] float2 (8KB) + KV[64*128] (32KB)
static constexpr int SMEM_BYTES = BM * SS * 4 + BM * DD * 8 + DD * NC * 4; // 106496

// ---- packed-f32x2 / shared-memory primitives ----
__device__ __forceinline__ unsigned long long lds_b64(unsigned a) {
    unsigned long long v;
    asm volatile("ld.shared.b64 %0, [%1];" : "=l"(v) : "r"(a));
    return v;
}
__device__ __forceinline__ float lds_f32(unsigned a) {
    float v;
    asm volatile("ld.shared.f32 %0, [%1];" : "=f"(v) : "r"(a));
    return v;
}
__device__ __forceinline__ void lds_v2u64(unsigned a, unsigned long long& x, unsigned long long& y) {
    asm volatile("ld.shared.v2.u64 {%0, %1}, [%2];" : "=l"(x), "=l"(y) : "r"(a));
}
// d.lo += a.lo*b.lo ; d.hi += a.hi*b.hi   (packed fp32x2 FMA, sm_100+)
__device__ __forceinline__ void ffma2(unsigned long long& d, unsigned long long a, unsigned long long b) {
    asm volatile("fma.rn.f32x2 %0, %1, %2, %0;" : "+l"(d) : "l"(a), "l"(b));
}
__device__ __forceinline__ unsigned long long pack2(float x) {
    unsigned long long v;
    asm volatile("mov.b64 %0, {%1, %1};" : "=l"(v) : "f"(x));
    return v;
}
__device__ __forceinline__ float2 unpk(unsigned long long v) {
    float2 r;
    asm volatile("mov.b64 {%0, %1}, %2;" : "=f"(r.x), "=f"(r.y) : "l"(v));
    return r;
}

__global__ __launch_bounds__(TB, 2)
void attn_fused_kernel(const float* __restrict__ q,      // [BH][S][D]
                       const float* __restrict__ kmat,   // [BH][D][S]  (already K^T-friendly)
                       const float* __restrict__ v,      // [BH][S][D]
                       const float* __restrict__ prev,   // [BH][S][S]
                       const float* __restrict__ mask,   // [S][S] broadcast
                       const float* __restrict__ scalep, // scalar
                       float* __restrict__ out_o,
                       float* __restrict__ out_w,
                       float* __restrict__ out_s)
{
    extern __shared__ float smem[];
    float*  Ss  = smem;                         // [BM][SS] scores -> weights
    float2* Qd  = (float2*)(smem + BM * SS);    // [BM][DD] Q duplicated (x,x) for f32x2
    float*  KV  = smem + BM * SS + BM * DD * 2; // [DD][NC] for K, reused as [NC][DD] for V

    const int tid   = threadIdx.x;
    const int bh    = blockIdx.y;
    const int qbase = blockIdx.x * BM;
    const float scale = scalep[0];

    const float* qg = q    + (size_t)bh * SS * DD;
    const float* kg = kmat + (size_t)bh * DD * SS;
    const float* vg = v    + (size_t)bh * SS * DD;
    const float* pg = prev + (size_t)bh * SS * SS;
    float* og = out_o + (size_t)bh * SS * DD;
    float* wg = out_w + (size_t)bh * SS * SS;
    float* sg = out_s + (size_t)bh * SS * SS;

    const unsigned ss_base = (unsigned)__cvta_generic_to_shared(Ss);
    const unsigned qd_base = (unsigned)__cvta_generic_to_shared(Qd);
    const unsigned kv_base = (unsigned)__cvta_generic_to_shared(KV);

    // ---- load Q tile, duplicated into both f32x2 lanes ----
    #pragma unroll
    for (int i = tid; i < BM * DD; i += TB) {
        int r = i >> 6, kk = i & 63;
        float val = qg[(size_t)(qbase + r) * DD + kk];
        Qd[r * DD + kk] = make_float2(val, val);
    }

    // ================= scores = (Q @ K) * mask * scale + prev =================
    // 256 threads: colg 0..31 -> 4 cols, rowg 0..7 -> 2 rows (warp == one row pair)
    const int colg = tid & 31;
    const int rowg = tid >> 5;
    const int r0   = rowg * 2;
    const unsigned qa0 = qd_base + (unsigned)(r0 * DD) * 8u;
    const unsigned qa1 = qa0 + DD * 8u;
    const unsigned bb0 = kv_base + (unsigned)(colg * 4) * 4u;

    for (int nb = 0; nb < SS; nb += NC) {
        __syncthreads();  // protects KV + (first iter) Qd
        // stage K chunk [DD][NC]
        #pragma unroll
        for (int i = tid; i < DD * (NC / 4); i += TB) {
            int row = i >> 5, c4 = i & 31;
            float4 t = *(const float4*)&kg[(size_t)row * SS + nb + c4 * 4];
            *(float4*)&KV[row * NC + c4 * 4] = t;
        }
        __syncthreads();

        unsigned long long acc00 = 0, acc01 = 0, acc10 = 0, acc11 = 0;
        #pragma unroll 16
        for (int kk = 0; kk < DD; kk++) {
            unsigned long long a0 = lds_b64(qa0 + kk * 8u);           // broadcast
            unsigned long long a1 = lds_b64(qa1 + kk * 8u);           // broadcast
            unsigned long long b01, b23;
            lds_v2u64(bb0 + (unsigned)kk * (NC * 4u), b01, b23);      // 16B vector
            ffma2(acc00, a0, b01); ffma2(acc01, a0, b23);
            ffma2(acc10, a1, b01); ffma2(acc11, a1, b23);
        }

        // epilogue: *mask*scale+prev, write scores to gmem + smem
        const int gc = nb + colg * 4;
        #pragma unroll
        for (int rr = 0; rr < 2; rr++) {
            float2 cA = unpk(rr ? acc10 : acc00);
            float2 cB = unpk(rr ? acc11 : acc01);
            const int gr = qbase + r0 + rr;
            float4 mk = *(const float4*)&mask[(size_t)gr * SS + gc];
            float4 pv = *(const float4*)&pg[(size_t)gr * SS + gc];
            float4 sc;
            sc.x = fmaf(cA.x * mk.x, scale, pv.x);
            sc.y = fmaf(cA.y * mk.y, scale, pv.y);
            sc.z = fmaf(cB.x * mk.z, scale, pv.z);
            sc.w = fmaf(cB.y * mk.w, scale, pv.w);
            *(float4*)&sg[(size_t)gr * SS + gc] = sc;
            *(float4*)&Ss[(r0 + rr) * SS + gc] = sc;
        }
    }
    __syncthreads();

    // ================= softmax per row (warp w handles rows w, w+8) =================
    const int warp = tid >> 5, lane = tid & 31;
    #pragma unroll
    for (int r = warp; r < BM; r += 8) {
        float* row = &Ss[r * SS];
        float m = -3.402823466e38f;
        for (int i = lane; i < SS; i += 32) m = fmaxf(m, row[i]);
        #pragma unroll
        for (int o = 16; o > 0; o >>= 1) m = fmaxf(m, __shfl_xor_sync(0xffffffffu, m, o));
        float sum = 0.f;
        for (int i = lane; i < SS; i += 32) {
            float e = exp2f((row[i] - m) * 1.4426950408889634f);
            row[i] = e; sum += e;
        }
        #pragma unroll
        for (int o = 16; o > 0; o >>= 1) sum += __shfl_xor_sync(0xffffffffu, sum, o);
        const float inv = 1.0f / sum;
        float* wrow = &wg[(size_t)(qbase + r) * SS];
        for (int i = lane; i < SS; i += 32) {
            float w = row[i] * inv;
            row[i] = w;          // keep normalized weights in smem for PV
            wrow[i] = w;         // write attn_weights
        }
    }

    // ================= out = W @ V =================
    // 256 threads: pcol 0..15 -> 4 cols, prow 0..15 -> 1 row. acc lives across chunks.
    const int pcol = tid & 15;
    const int prow = tid >> 4;
    unsigned long long o01 = 0, o23 = 0;
    const unsigned va0 = kv_base + (unsigned)(pcol * 4) * 4u;
    for (int sb = 0; sb < SS; sb += NC) {
        __syncthreads();  // orders softmax writes / prior-chunk V reads before restage
        #pragma unroll
        for (int i = tid; i < NC * (DD / 4); i += TB) {
            int row = i >> 4, c4 = i & 15;
            float4 t = *(const float4*)&vg[(size_t)(sb + row) * DD + c4 * 4];
            *(float4*)&KV[row * DD + c4 * 4] = t;
        }
        __syncthreads();
        const unsigned wa = ss_base + (unsigned)(prow * SS + sb) * 4u;
        #pragma unroll 16
        for (int s = 0; s < NC; s++) {
            float a = lds_f32(wa + s * 4u);                         // broadcast
            unsigned long long ap = pack2(a);
            unsigned long long b01, b23;
            lds_v2u64(va0 + (unsigned)s * (DD * 4u), b01, b23);
            ffma2(o01, ap, b01); ffma2(o23, ap, b23);
        }
    }
    float2 r01 = unpk(o01), r23 = unpk(o23);
    float4 ov = make_float4(r01.x, r01.y, r23.x, r23.y);
    *(float4*)&og[(size_t)(qbase + prow) * DD + pcol * 4] = ov;
}

extern "C" void kernel_launch(void* const* d_in, const int* in_sizes, int n_in,
                              void* d_out, int out_size) {
    (void)in_sizes; (void)n_in; (void)out_size;
    const float* q     = (const float*)d_in[0];
    const float* k     = (const float*)d_in[1];
    const float* v     = (const float*)d_in[2];
    const float* prev  = (const float*)d_in[3];
    const float* mask  = (const float*)d_in[4];
    const float* scale = (const float*)d_in[5];

    float* out   = (float*)d_out;
    float* out_o = out;                     // [B,H,S,D]
    float* out_w = out + O_ELEMS;           // [B,H,S,S]
    float* out_s = out_w + W_ELEMS;         // [B,H,S,S]

    cudaFuncSetAttribute(attn_fused_kernel,
                         cudaFuncAttributeMaxDynamicSharedMemorySize, SMEM_BYTES);

    dim3 grid(SS / BM, NBH);  // (64, 128) = 8192 blocks
    attn_fused_kernel<<<grid, TB, SMEM_BYTES>>>(q, k, v, prev, mask, scale,
                                                out_o, out_w, out_s);
}

// round 14
// speedup vs baseline: 1.3197x; 1.3197x over previous
#include <cuda_runtime.h>
#include <cstdint>

// Problem constants (B=8, H=16, S=1024, D=64)
#define TB   256      // threads per block
#define BM   16       // query rows per block
#define NC   512      // K/V chunk staged in smem
#define SS   1024     // seq len
#define SSP  1028     // padded Ss row stride (floats) -> bank-conflict-free PV A loads
#define DD   64       // head dim
#define NBH  128      // B*H
#define QDS  18       // Qdup stride (float2 per k-index), even for 16B-aligned v2.u64

static constexpr size_t O_ELEMS = (size_t)NBH * SS * DD;   // 8388608
static constexpr size_t W_ELEMS = (size_t)NBH * SS * SS;   // 134217728

// smem layout (floats): Ss[16][1028] | Qdup[64][18]x2 (reused as Sinv[16]) | KV[512*64]
static constexpr int OFF_QD = BM * SSP;                 // 16448
static constexpr int OFF_KV = OFF_QD + 2 * DD * QDS;    // 16448 + 2304 = 18752
static constexpr int SMEM_FLOATS = OFF_KV + NC * DD;    // + 32768 = 51520
static constexpr int SMEM_BYTES  = SMEM_FLOATS * 4;     // 206080 (<227KB)

typedef unsigned long long u64;

// ---- packed-f32x2 / shared-memory primitives ----
__device__ __forceinline__ float lds_f32(unsigned a) {
    float v; asm volatile("ld.shared.f32 %0, [%1];" : "=f"(v) : "r"(a)); return v;
}
__device__ __forceinline__ void lds_v2u64(unsigned a, u64& x, u64& y) {
    asm volatile("ld.shared.v2.u64 {%0, %1}, [%2];" : "=l"(x), "=l"(y) : "r"(a));
}
__device__ __forceinline__ void ffma2(u64& d, u64 a, u64 b) {
    asm volatile("fma.rn.f32x2 %0, %1, %2, %0;" : "+l"(d) : "l"(a), "l"(b));
}
__device__ __forceinline__ void addf2(u64& d, u64 a) {
    asm volatile("add.rn.f32x2 %0, %0, %1;" : "+l"(d) : "l"(a));
}
__device__ __forceinline__ u64 mulf2(u64 a, u64 b) {
    u64 d; asm volatile("mul.rn.f32x2 %0, %1, %2;" : "=l"(d) : "l"(a), "l"(b)); return d;
}
__device__ __forceinline__ u64 pack2(float x) {
    u64 v; asm volatile("mov.b64 %0, {%1, %1};" : "=l"(v) : "f"(x)); return v;
}
__device__ __forceinline__ float2 unpk(u64 v) {
    float2 r; asm volatile("mov.b64 {%0, %1}, %2;" : "=f"(r.x), "=f"(r.y) : "l"(v)); return r;
}

__global__ __launch_bounds__(TB, 1)
void attn_fused_v2(const float* __restrict__ q,      // [BH][S][D]
                   const float* __restrict__ kmat,   // [BH][D][S]
                   const float* __restrict__ v,      // [BH][S][D]
                   const float* __restrict__ prev,   // [BH][S][S]
                   const float* __restrict__ mask,   // [S][S] broadcast
                   const float* __restrict__ scalep,
                   float* __restrict__ out_o,
                   float* __restrict__ out_w,
                   float* __restrict__ out_s)
{
    extern __shared__ float smem[];
    float*  Ss   = smem;                       // [BM][SSP] scores -> exp values
    float2* Qd   = (float2*)(smem + OFF_QD);   // [DD][QDS] transposed, duplicated Q
    float*  Sinv = smem + OFF_QD;              // reused after QK phase
    float*  KV   = smem + OFF_KV;              // K: [64][512], V: [512][64], partials: u64[8*512]

    const int tid   = threadIdx.x;
    const int bh    = blockIdx.y;
    const int qbase = blockIdx.x * BM;
    const float scale = scalep[0];

    const float* qg = q    + (size_t)bh * SS * DD;
    const float* kg = kmat + (size_t)bh * DD * SS;
    const float* vg = v    + (size_t)bh * SS * DD;
    const float* pg = prev + (size_t)bh * SS * SS;
    float* og = out_o + (size_t)bh * SS * DD;
    float* wg = out_w + (size_t)bh * SS * SS;
    float* sg = out_s + (size_t)bh * SS * SS;

    const unsigned sm_b = (unsigned)__cvta_generic_to_shared(smem);
    const unsigned ss_b = sm_b;
    const unsigned qd_b = sm_b + OFF_QD * 4u;
    const unsigned kv_b = sm_b + OFF_KV * 4u;

    // ---- load Q tile: transposed + duplicated into f32x2 lanes ----
    #pragma unroll
    for (int i = tid; i < BM * DD; i += TB) {
        int r = i >> 6, kk = i & 63;                 // coalesced gmem read
        float val = qg[(size_t)(qbase + r) * DD + kk];
        Qd[kk * QDS + r] = make_float2(val, val);
    }

    // ================= scores = (Q @ K) * mask * scale + prev =================
    // 256 threads = 2 rowg (8 rows each) x 128 colg (4 cols each). Warp: colg contiguous.
    const int rowg = tid >> 7;          // 0..1
    const int colg = tid & 127;         // 0..127
    const unsigned qa = qd_b + (unsigned)(rowg * 8) * 8u;
    const unsigned ba = kv_b + (unsigned)(colg * 4) * 4u;

    for (int nb = 0; nb < SS; nb += NC) {
        __syncthreads();  // protects KV (+Qd on first iter)
        #pragma unroll
        for (int i = tid; i < DD * (NC / 4); i += TB) {      // 8192 float4s
            int row = i >> 7, c4 = i & 127;
            float4 t = *(const float4*)&kg[(size_t)row * SS + nb + c4 * 4];
            *(float4*)&KV[row * NC + c4 * 4] = t;
        }
        __syncthreads();

        u64 acc[8][2];
        #pragma unroll
        for (int r = 0; r < 8; r++) { acc[r][0] = 0; acc[r][1] = 0; }

        #pragma unroll 4
        for (int kk = 0; kk < DD; kk++) {
            u64 a0,a1,a2,a3,a4,a5,a6,a7, bx,by;
            const unsigned qk = qa + (unsigned)kk * (QDS * 8u);
            lds_v2u64(qk +  0u, a0, a1);      // rows 0,1 (duplicated pairs) - broadcast
            lds_v2u64(qk + 16u, a2, a3);
            lds_v2u64(qk + 32u, a4, a5);
            lds_v2u64(qk + 48u, a6, a7);
            lds_v2u64(ba + (unsigned)kk * (NC * 4u), bx, by); // 4 cols, 16B vector
            ffma2(acc[0][0], a0, bx); ffma2(acc[0][1], a0, by);
            ffma2(acc[1][0], a1, bx); ffma2(acc[1][1], a1, by);
            ffma2(acc[2][0], a2, bx); ffma2(acc[2][1], a2, by);
            ffma2(acc[3][0], a3, bx); ffma2(acc[3][1], a3, by);
            ffma2(acc[4][0], a4, bx); ffma2(acc[4][1], a4, by);
            ffma2(acc[5][0], a5, bx); ffma2(acc[5][1], a5, by);
            ffma2(acc[6][0], a6, bx); ffma2(acc[6][1], a6, by);
            ffma2(acc[7][0], a7, bx); ffma2(acc[7][1], a7, by);
        }

        // epilogue: *mask*scale + prev; write scores to gmem + smem
        const int gc = nb + colg * 4;
        #pragma unroll
        for (int rr = 0; rr < 8; rr++) {
            const int lr = rowg * 8 + rr;
            const int gr = qbase + lr;
            float2 cA = unpk(acc[rr][0]);
            float2 cB = unpk(acc[rr][1]);
            float4 mk = *(const float4*)&mask[(size_t)gr * SS + gc];
            float4 pv = *(const float4*)&pg[(size_t)gr * SS + gc];
            float4 sc;
            sc.x = fmaf(cA.x * mk.x, scale, pv.x);
            sc.y = fmaf(cA.y * mk.y, scale, pv.y);
            sc.z = fmaf(cB.x * mk.z, scale, pv.z);
            sc.w = fmaf(cB.y * mk.w, scale, pv.w);
            *(float4*)&sg[(size_t)gr * SS + gc] = sc;
            *(float4*)&Ss[lr * SSP + gc] = sc;
        }
    }
    __syncthreads();

    // ================= softmax per row (warp w: rows w, w+8) =================
    // Ss keeps UNNORMALIZED exp; 1/sum stored in Sinv and applied after PV.
    const int warp = tid >> 5, lane = tid & 31;
    #pragma unroll
    for (int r = warp; r < BM; r += 8) {
        float* row = &Ss[r * SSP];
        float m = -3.402823466e38f;
        #pragma unroll 8
        for (int i = lane; i < SS; i += 32) m = fmaxf(m, row[i]);
        #pragma unroll
        for (int o = 16; o > 0; o >>= 1) m = fmaxf(m, __shfl_xor_sync(0xffffffffu, m, o));
        float sum = 0.f;
        #pragma unroll 8
        for (int i = lane; i < SS; i += 32) {
            float e = exp2f((row[i] - m) * 1.4426950408889634f);
            row[i] = e; sum += e;
        }
        #pragma unroll
        for (int o = 16; o > 0; o >>= 1) sum += __shfl_xor_sync(0xffffffffu, sum, o);
        const float inv = 1.0f / sum;
        float* wrow = &wg[(size_t)(qbase + r) * SS];
        #pragma unroll 8
        for (int i = lane; i < SS; i += 32) wrow[i] = row[i] * inv;
        if (lane == 0) Sinv[r] = inv;
    }

    // ================= out = E @ V (split-S over 8 warps, inv folded at end) ====
    // Each warp owns S/8; lane = rowg2(4) x colg2(8); thread tile = rows {rowg2+4j} x 8 cols.
    const int rowg2 = lane >> 3;   // 0..3
    const int colg2 = lane & 7;    // 0..7
    u64 o00=0,o01=0,o02=0,o03=0, o10=0,o11=0,o12=0,o13=0,
        o20=0,o21=0,o22=0,o23=0, o30=0,o31=0,o32=0,o33=0;

    for (int sb = 0; sb < SS; sb += NC) {
        __syncthreads();   // softmax done (first iter) / prior chunk V reads done
        #pragma unroll
        for (int i = tid; i < NC * (DD / 4); i += TB) {      // 8192 float4s
            int row = i >> 4, c4 = i & 15;
            float4 t = *(const float4*)&vg[(size_t)(sb + row) * DD + c4 * 4];
            *(float4*)&KV[row * DD + c4 * 4] = t;
        }
        __syncthreads();

        const int scol0 = sb + warp * (NC / 8);              // this warp's s-slice
        const unsigned wa0 = ss_b + (unsigned)((rowg2 + 0) * SSP + scol0) * 4u;
        const unsigned wa1 = ss_b + (unsigned)((rowg2 + 4) * SSP + scol0) * 4u;
        const unsigned wa2 = ss_b + (unsigned)((rowg2 + 8) * SSP + scol0) * 4u;
        const unsigned wa3 = ss_b + (unsigned)((rowg2 +12) * SSP + scol0) * 4u;
        const unsigned vb  = kv_b + (unsigned)((warp * (NC / 8)) * DD + colg2 * 8) * 4u;

        #pragma unroll 4
        for (int i = 0; i < NC / 8; i++) {                   // 64 s-steps
            u64 b0x, b0y, b1x, b1y;
            const unsigned va = vb + (unsigned)i * (DD * 4u);
            lds_v2u64(va,       b0x, b0y);                   // cols 0..3
            lds_v2u64(va + 16u, b1x, b1y);                   // cols 4..7
            u64 a0 = pack2(lds_f32(wa0 + i * 4u));
            u64 a1 = pack2(lds_f32(wa1 + i * 4u));
            u64 a2 = pack2(lds_f32(wa2 + i * 4u));
            u64 a3 = pack2(lds_f32(wa3 + i * 4u));
            ffma2(o00,a0,b0x); ffma2(o01,a0,b0y); ffma2(o02,a0,b1x); ffma2(o03,a0,b1y);
            ffma2(o10,a1,b0x); ffma2(o11,a1,b0y); ffma2(o12,a1,b1x); ffma2(o13,a1,b1y);
            ffma2(o20,a2,b0x); ffma2(o21,a2,b0y); ffma2(o22,a2,b1x); ffma2(o23,a2,b1y);
            ffma2(o30,a3,b0x); ffma2(o31,a3,b0y); ffma2(o32,a3,b1x); ffma2(o33,a3,b1y);
        }
    }

    // ---- cross-warp reduction of PV partials through smem (reuse KV) ----
    __syncthreads();
    u64* Pu = (u64*)KV;   // [8 warps][16 rows][32 col-pairs] = 4096 u64
    {
        const int base = warp * 512 + colg2 * 4;
        #pragma unroll
        for (int j = 0; j < 4; j++) {
            const int rb = (rowg2 + 4 * j) * 32 + base;
            u64* p = &Pu[rb];
            p[0] = (j==0? o00 : j==1? o10 : j==2? o20 : o30);
            p[1] = (j==0? o01 : j==1? o11 : j==2? o21 : o31);
            p[2] = (j==0? o02 : j==1? o12 : j==2? o22 : o32);
            p[3] = (j==0? o03 : j==1? o13 : j==2? o23 : o33);
        }
    }
    __syncthreads();
    #pragma unroll
    for (int t = tid; t < 512; t += TB) {        // 2 iterations
        const int r = t >> 5, cp = t & 31;
        u64 s64 = Pu[t];
        #pragma unroll
        for (int w2 = 1; w2 < 8; w2++) addf2(s64, Pu[w2 * 512 + t]);
        s64 = mulf2(s64, pack2(Sinv[r]));
        *(u64*)&og[(size_t)(qbase + r) * DD + cp * 2] = s64;
    }
}

extern "C" void kernel_launch(void* const* d_in, const int* in_sizes, int n_in,
                              void* d_out, int out_size) {
    (void)in_sizes; (void)n_in; (void)out_size;
    const float* q     = (const float*)d_in[0];
    const float* k     = (const float*)d_in[1];
    const float* v     = (const float*)d_in[2];
    const float* prev  = (const float*)d_in[3];
    const float* mask  = (const float*)d_in[4];
    const float* scale = (const float*)d_in[5];

    float* out   = (float*)d_out;
    float* out_o = out;                     // [B,H,S,D]
    float* out_w = out + O_ELEMS;           // [B,H,S,S]
    float* out_s = out_w + W_ELEMS;         // [B,H,S,S]

    cudaFuncSetAttribute(attn_fused_v2,
                         cudaFuncAttributeMaxDynamicSharedMemorySize, SMEM_BYTES);

    dim3 grid(SS / BM, NBH);  // (64, 128) = 8192 blocks
    attn_fused_v2<<<grid, TB, SMEM_BYTES>>>(q, k, v, prev, mask, scale,
                                            out_o, out_w, out_s);
}

// round 15
// speedup vs baseline: 1.3201x; 1.0004x over previous
#include <cuda_runtime.h>
#include <cstdint>

// Problem constants (B=8, H=16, S=1024, D=64)
#define TB   256      // threads per block
#define BM   16       // query rows per block
#define NC   512      // K/V chunk staged in smem
#define SS   1024     // seq len
#define SSP  1028     // padded Ss row stride (floats) -> bank-conflict-free PV A loads
#define DD   64       // head dim
#define NBH  128      // B*H
#define QDS  18       // Qdup stride (float2 per k-index), even for 16B-aligned v2.u64

static constexpr size_t O_ELEMS = (size_t)NBH * SS * DD;   // 8388608
static constexpr size_t W_ELEMS = (size_t)NBH * SS * SS;   // 134217728

// smem layout (floats): Ss[16][1028] | Qdup[64][18]x2 (reused as Sinv[16]) | KV[512*64]
static constexpr int OFF_QD = BM * SSP;                 // 16448
static constexpr int OFF_KV = OFF_QD + 2 * DD * QDS;    // 16448 + 2304 = 18752
static constexpr int SMEM_FLOATS = OFF_KV + NC * DD;    // + 32768 = 51520
static constexpr int SMEM_BYTES  = SMEM_FLOATS * 4;     // 206080 (<227KB)

typedef unsigned long long u64;

// ---- packed-f32x2 / shared-memory primitives ----
__device__ __forceinline__ float lds_f32(unsigned a) {
    float v; asm volatile("ld.shared.f32 %0, [%1];" : "=f"(v) : "r"(a)); return v;
}
__device__ __forceinline__ void lds_v2u64(unsigned a, u64& x, u64& y) {
    asm volatile("ld.shared.v2.u64 {%0, %1}, [%2];" : "=l"(x), "=l"(y) : "r"(a));
}
__device__ __forceinline__ void ffma2(u64& d, u64 a, u64 b) {
    asm volatile("fma.rn.f32x2 %0, %1, %2, %0;" : "+l"(d) : "l"(a), "l"(b));
}
__device__ __forceinline__ void addf2(u64& d, u64 a) {
    asm volatile("add.rn.f32x2 %0, %0, %1;" : "+l"(d) : "l"(a));
}
__device__ __forceinline__ u64 mulf2(u64 a, u64 b) {
    u64 d; asm volatile("mul.rn.f32x2 %0, %1, %2;" : "=l"(d) : "l"(a), "l"(b)); return d;
}
__device__ __forceinline__ u64 pack2(float x) {
    u64 v; asm volatile("mov.b64 %0, {%1, %1};" : "=l"(v) : "f"(x)); return v;
}
__device__ __forceinline__ float2 unpk(u64 v) {
    float2 r; asm volatile("mov.b64 {%0, %1}, %2;" : "=f"(r.x), "=f"(r.y) : "l"(v)); return r;
}

__global__ __launch_bounds__(TB, 1)
void attn_fused_v2(const float* __restrict__ q,      // [BH][S][D]
                   const float* __restrict__ kmat,   // [BH][D][S]
                   const float* __restrict__ v,      // [BH][S][D]
                   const float* __restrict__ prev,   // [BH][S][S]
                   const float* __restrict__ mask,   // [S][S] broadcast
                   const float* __restrict__ scalep,
                   float* __restrict__ out_o,
                   float* __restrict__ out_w,
                   float* __restrict__ out_s)
{
    extern __shared__ float smem[];
    float*  Ss   = smem;                       // [BM][SSP] scores -> exp values
    float2* Qd   = (float2*)(smem + OFF_QD);   // [DD][QDS] transposed, duplicated Q
    float*  Sinv = smem + OFF_QD;              // reused after QK phase
    float*  KV   = smem + OFF_KV;              // K: [64][512], V: [512][64], partials: u64[8*512]

    const int tid   = threadIdx.x;
    const int bh    = blockIdx.y;
    const int qbase = blockIdx.x * BM;
    const float scale = scalep[0];

    const float* qg = q    + (size_t)bh * SS * DD;
    const float* kg = kmat + (size_t)bh * DD * SS;
    const float* vg = v    + (size_t)bh * SS * DD;
    const float* pg = prev + (size_t)bh * SS * SS;
    float* og = out_o + (size_t)bh * SS * DD;
    float* wg = out_w + (size_t)bh * SS * SS;
    float* sg = out_s + (size_t)bh * SS * SS;

    const unsigned sm_b = (unsigned)__cvta_generic_to_shared(smem);
    const unsigned ss_b = sm_b;
    const unsigned qd_b = sm_b + OFF_QD * 4u;
    const unsigned kv_b = sm_b + OFF_KV * 4u;

    // ---- load Q tile: transposed + duplicated into f32x2 lanes ----
    #pragma unroll
    for (int i = tid; i < BM * DD; i += TB) {
        int r = i >> 6, kk = i & 63;                 // coalesced gmem read
        float val = qg[(size_t)(qbase + r) * DD + kk];
        Qd[kk * QDS + r] = make_float2(val, val);
    }

    // ================= scores = (Q @ K) * mask * scale + prev =================
    // 256 threads = 2 rowg (8 rows each) x 128 colg (4 cols each). Warp: colg contiguous.
    const int rowg = tid >> 7;          // 0..1
    const int colg = tid & 127;         // 0..127
    const unsigned qa = qd_b + (unsigned)(rowg * 8) * 8u;
    const unsigned ba = kv_b + (unsigned)(colg * 4) * 4u;

    for (int nb = 0; nb < SS; nb += NC) {
        __syncthreads();  // protects KV (+Qd on first iter)
        #pragma unroll
        for (int i = tid; i < DD * (NC / 4); i += TB) {      // 8192 float4s
            int row = i >> 7, c4 = i & 127;
            float4 t = *(const float4*)&kg[(size_t)row * SS + nb + c4 * 4];
            *(float4*)&KV[row * NC + c4 * 4] = t;
        }
        __syncthreads();

        u64 acc[8][2];
        #pragma unroll
        for (int r = 0; r < 8; r++) { acc[r][0] = 0; acc[r][1] = 0; }

        #pragma unroll 4
        for (int kk = 0; kk < DD; kk++) {
            u64 a0,a1,a2,a3,a4,a5,a6,a7, bx,by;
            const unsigned qk = qa + (unsigned)kk * (QDS * 8u);
            lds_v2u64(qk +  0u, a0, a1);      // rows 0,1 (duplicated pairs) - broadcast
            lds_v2u64(qk + 16u, a2, a3);
            lds_v2u64(qk + 32u, a4, a5);
            lds_v2u64(qk + 48u, a6, a7);
            lds_v2u64(ba + (unsigned)kk * (NC * 4u), bx, by); // 4 cols, 16B vector
            ffma2(acc[0][0], a0, bx); ffma2(acc[0][1], a0, by);
            ffma2(acc[1][0], a1, bx); ffma2(acc[1][1], a1, by);
            ffma2(acc[2][0], a2, bx); ffma2(acc[2][1], a2, by);
            ffma2(acc[3][0], a3, bx); ffma2(acc[3][1], a3, by);
            ffma2(acc[4][0], a4, bx); ffma2(acc[4][1], a4, by);
            ffma2(acc[5][0], a5, bx); ffma2(acc[5][1], a5, by);
            ffma2(acc[6][0], a6, bx); ffma2(acc[6][1], a6, by);
            ffma2(acc[7][0], a7, bx); ffma2(acc[7][1], a7, by);
        }

        // epilogue: *mask*scale + prev; write scores to gmem + smem
        const int gc = nb + colg * 4;
        #pragma unroll
        for (int rr = 0; rr < 8; rr++) {
            const int lr = rowg * 8 + rr;
            const int gr = qbase + lr;
            float2 cA = unpk(acc[rr][0]);
            float2 cB = unpk(acc[rr][1]);
            float4 mk = *(const float4*)&mask[(size_t)gr * SS + gc];
            float4 pv = *(const float4*)&pg[(size_t)gr * SS + gc];
            float4 sc;
            sc.x = fmaf(cA.x * mk.x, scale, pv.x);
            sc.y = fmaf(cA.y * mk.y, scale, pv.y);
            sc.z = fmaf(cB.x * mk.z, scale, pv.z);
            sc.w = fmaf(cB.y * mk.w, scale, pv.w);
            *(float4*)&sg[(size_t)gr * SS + gc] = sc;
            *(float4*)&Ss[lr * SSP + gc] = sc;
        }
    }
    __syncthreads();

    // ================= softmax per row (warp w: rows w, w+8) =================
    // Ss keeps UNNORMALIZED exp; 1/sum stored in Sinv and applied after PV.
    const int warp = tid >> 5, lane = tid & 31;
    #pragma unroll
    for (int r = warp; r < BM; r += 8) {
        float* row = &Ss[r * SSP];
        float m = -3.402823466e38f;
        #pragma unroll 8
        for (int i = lane; i < SS; i += 32) m = fmaxf(m, row[i]);
        #pragma unroll
        for (int o = 16; o > 0; o >>= 1) m = fmaxf(m, __shfl_xor_sync(0xffffffffu, m, o));
        float sum = 0.f;
        #pragma unroll 8
        for (int i = lane; i < SS; i += 32) {
            float e = exp2f((row[i] - m) * 1.4426950408889634f);
            row[i] = e; sum += e;
        }
        #pragma unroll
        for (int o = 16; o > 0; o >>= 1) sum += __shfl_xor_sync(0xffffffffu, sum, o);
        const float inv = 1.0f / sum;
        float* wrow = &wg[(size_t)(qbase + r) * SS];
        #pragma unroll 8
        for (int i = lane; i < SS; i += 32) wrow[i] = row[i] * inv;
        if (lane == 0) Sinv[r] = inv;
    }

    // ================= out = E @ V (split-S over 8 warps, inv folded at end) ====
    // Each warp owns S/8; lane = rowg2(4) x colg2(8); thread tile = rows {rowg2+4j} x 8 cols.
    const int rowg2 = lane >> 3;   // 0..3
    const int colg2 = lane & 7;    // 0..7
    u64 o00=0,o01=0,o02=0,o03=0, o10=0,o11=0,o12=0,o13=0,
        o20=0,o21=0,o22=0,o23=0, o30=0,o31=0,o32=0,o33=0;

    for (int sb = 0; sb < SS; sb += NC) {
        __syncthreads();   // softmax done (first iter) / prior chunk V reads done
        #pragma unroll
        for (int i = tid; i < NC * (DD / 4); i += TB) {      // 8192 float4s
            int row = i >> 4, c4 = i & 15;
            float4 t = *(const float4*)&vg[(size_t)(sb + row) * DD + c4 * 4];
            *(float4*)&KV[row * DD + c4 * 4] = t;
        }
        __syncthreads();

        const int scol0 = sb + warp * (NC / 8);              // this warp's s-slice
        const unsigned wa0 = ss_b + (unsigned)((rowg2 + 0) * SSP + scol0) * 4u;
        const unsigned wa1 = ss_b + (unsigned)((rowg2 + 4) * SSP + scol0) * 4u;
        const unsigned wa2 = ss_b + (unsigned)((rowg2 + 8) * SSP + scol0) * 4u;
        const unsigned wa3 = ss_b + (unsigned)((rowg2 +12) * SSP + scol0) * 4u;
        const unsigned vb  = kv_b + (unsigned)((warp * (NC / 8)) * DD + colg2 * 8) * 4u;

        #pragma unroll 4
        for (int i = 0; i < NC / 8; i++) {                   // 64 s-steps
            u64 b0x, b0y, b1x, b1y;
            const unsigned va = vb + (unsigned)i * (DD * 4u);
            lds_v2u64(va,       b0x, b0y);                   // cols 0..3
            lds_v2u64(va + 16u, b1x, b1y);                   // cols 4..7
            u64 a0 = pack2(lds_f32(wa0 + i * 4u));
            u64 a1 = pack2(lds_f32(wa1 + i * 4u));
            u64 a2 = pack2(lds_f32(wa2 + i * 4u));
            u64 a3 = pack2(lds_f32(wa3 + i * 4u));
            ffma2(o00,a0,b0x); ffma2(o01,a0,b0y); ffma2(o02,a0,b1x); ffma2(o03,a0,b1y);
            ffma2(o10,a1,b0x); ffma2(o11,a1,b0y); ffma2(o12,a1,b1x); ffma2(o13,a1,b1y);
            ffma2(o20,a2,b0x); ffma2(o21,a2,b0y); ffma2(o22,a2,b1x); ffma2(o23,a2,b1y);
            ffma2(o30,a3,b0x); ffma2(o31,a3,b0y); ffma2(o32,a3,b1x); ffma2(o33,a3,b1y);
        }
    }

    // ---- cross-warp reduction of PV partials through smem (reuse KV) ----
    __syncthreads();
    u64* Pu = (u64*)KV;   // [8 warps][16 rows][32 col-pairs] = 4096 u64
    {
        const int base = warp * 512 + colg2 * 4;
        #pragma unroll
        for (int j = 0; j < 4; j++) {
            const int rb = (rowg2 + 4 * j) * 32 + base;
            u64* p = &Pu[rb];
            p[0] = (j==0? o00 : j==1? o10 : j==2? o20 : o30);
            p[1] = (j==0? o01 : j==1? o11 : j==2? o21 : o31);
            p[2] = (j==0? o02 : j==1? o12 : j==2? o22 : o32);
            p[3] = (j==0? o03 : j==1? o13 : j==2? o23 : o33);
        }
    }
    __syncthreads();
    #pragma unroll
    for (int t = tid; t < 512; t += TB) {        // 2 iterations
        const int r = t >> 5, cp = t & 31;
        u64 s64 = Pu[t];
        #pragma unroll
        for (int w2 = 1; w2 < 8; w2++) addf2(s64, Pu[w2 * 512 + t]);
        s64 = mulf2(s64, pack2(Sinv[r]));
        *(u64*)&og[(size_t)(qbase + r) * DD + cp * 2] = s64;
    }
}

extern "C" void kernel_launch(void* const* d_in, const int* in_sizes, int n_in,
                              void* d_out, int out_size) {
    (void)in_sizes; (void)n_in; (void)out_size;
    const float* q     = (const float*)d_in[0];
    const float* k     = (const float*)d_in[1];
    const float* v     = (const float*)d_in[2];
    const float* prev  = (const float*)d_in[3];
    const float* mask  = (const float*)d_in[4];
    const float* scale = (const float*)d_in[5];

    float* out   = (float*)d_out;
    float* out_o = out;                     // [B,H,S,D]
    float* out_w = out + O_ELEMS;           // [B,H,S,S]
    float* out_s = out_w + W_ELEMS;         // [B,H,S,S]

    cudaFuncSetAttribute(attn_fused_v2,
                         cudaFuncAttributeMaxDynamicSharedMemorySize, SMEM_BYTES);

    dim3 grid(SS / BM, NBH);  // (64, 128) = 8192 blocks
    attn_fused_v2<<<grid, TB, SMEM_BYTES>>>(q, k, v, prev, mask, scale,
                                            out_o, out_w, out_s);
}

// round 16
// speedup vs baseline: 1.3203x; 1.0001x over previous
#include <cuda_runtime.h>
#include <cstdint>

// Problem constants (B=8, H=16, S=1024, D=64)
#define TB   256      // threads per block
#define BM   16       // query rows per block
#define NC   512      // K/V chunk staged in smem
#define SS   1024     // seq len
#define SSP  1028     // padded Ss row stride (floats) -> bank-conflict-free PV A loads
#define DD   64       // head dim
#define NBH  128      // B*H
#define QDS  18       // Qdup stride (float2 per k-index), even for 16B-aligned v2.u64

static constexpr size_t O_ELEMS = (size_t)NBH * SS * DD;   // 8388608
static constexpr size_t W_ELEMS = (size_t)NBH * SS * SS;   // 134217728

// smem layout (floats): Ss[16][1028] | Qdup[64][18]x2 (reused as Sinv[16]) | KV[512*64]
static constexpr int OFF_QD = BM * SSP;                 // 16448
static constexpr int OFF_KV = OFF_QD + 2 * DD * QDS;    // 16448 + 2304 = 18752
static constexpr int SMEM_FLOATS = OFF_KV + NC * DD;    // + 32768 = 51520
static constexpr int SMEM_BYTES  = SMEM_FLOATS * 4;     // 206080 (<227KB)

typedef unsigned long long u64;

// ---- packed-f32x2 / shared-memory primitives ----
__device__ __forceinline__ float lds_f32(unsigned a) {
    float v; asm volatile("ld.shared.f32 %0, [%1];" : "=f"(v) : "r"(a)); return v;
}
__device__ __forceinline__ void lds_v2u64(unsigned a, u64& x, u64& y) {
    asm volatile("ld.shared.v2.u64 {%0, %1}, [%2];" : "=l"(x), "=l"(y) : "r"(a));
}
__device__ __forceinline__ void ffma2(u64& d, u64 a, u64 b) {
    asm volatile("fma.rn.f32x2 %0, %1, %2, %0;" : "+l"(d) : "l"(a), "l"(b));
}
__device__ __forceinline__ void addf2(u64& d, u64 a) {
    asm volatile("add.rn.f32x2 %0, %0, %1;" : "+l"(d) : "l"(a));
}
__device__ __forceinline__ u64 mulf2(u64 a, u64 b) {
    u64 d; asm volatile("mul.rn.f32x2 %0, %1, %2;" : "=l"(d) : "l"(a), "l"(b)); return d;
}
__device__ __forceinline__ u64 pack2(float x) {
    u64 v; asm volatile("mov.b64 %0, {%1, %1};" : "=l"(v) : "f"(x)); return v;
}
__device__ __forceinline__ float2 unpk(u64 v) {
    float2 r; asm volatile("mov.b64 {%0, %1}, %2;" : "=f"(r.x), "=f"(r.y) : "l"(v)); return r;
}

__global__ __launch_bounds__(TB, 1)
void attn_fused_v2(const float* __restrict__ q,      // [BH][S][D]
                   const float* __restrict__ kmat,   // [BH][D][S]
                   const float* __restrict__ v,      // [BH][S][D]
                   const float* __restrict__ prev,   // [BH][S][S]
                   const float* __restrict__ mask,   // [S][S] broadcast
                   const float* __restrict__ scalep,
                   float* __restrict__ out_o,
                   float* __restrict__ out_w,
                   float* __restrict__ out_s)
{
    extern __shared__ float smem[];
    float*  Ss   = smem;                       // [BM][SSP] scores -> exp values
    float2* Qd   = (float2*)(smem + OFF_QD);   // [DD][QDS] transposed, duplicated Q
    float*  Sinv = smem + OFF_QD;              // reused after QK phase
    float*  KV   = smem + OFF_KV;              // K: [64][512], V: [512][64], partials: u64[8*512]

    const int tid   = threadIdx.x;
    const int bh    = blockIdx.y;
    const int qbase = blockIdx.x * BM;
    const float scale = scalep[0];

    const float* qg = q    + (size_t)bh * SS * DD;
    const float* kg = kmat + (size_t)bh * DD * SS;
    const float* vg = v    + (size_t)bh * SS * DD;
    const float* pg = prev + (size_t)bh * SS * SS;
    float* og = out_o + (size_t)bh * SS * DD;
    float* wg = out_w + (size_t)bh * SS * SS;
    float* sg = out_s + (size_t)bh * SS * SS;

    const unsigned sm_b = (unsigned)__cvta_generic_to_shared(smem);
    const unsigned ss_b = sm_b;
    const unsigned qd_b = sm_b + OFF_QD * 4u;
    const unsigned kv_b = sm_b + OFF_KV * 4u;

    // ---- load Q tile: transposed + duplicated into f32x2 lanes ----
    #pragma unroll
    for (int i = tid; i < BM * DD; i += TB) {
        int r = i >> 6, kk = i & 63;                 // coalesced gmem read
        float val = qg[(size_t)(qbase + r) * DD + kk];
        Qd[kk * QDS + r] = make_float2(val, val);
    }

    // ================= scores = (Q @ K) * mask * scale + prev =================
    // 256 threads = 2 rowg (8 rows each) x 128 colg (4 cols each). Warp: colg contiguous.
    const int rowg = tid >> 7;          // 0..1
    const int colg = tid & 127;         // 0..127
    const unsigned qa = qd_b + (unsigned)(rowg * 8) * 8u;
    const unsigned ba = kv_b + (unsigned)(colg * 4) * 4u;

    for (int nb = 0; nb < SS; nb += NC) {
        __syncthreads();  // protects KV (+Qd on first iter)
        #pragma unroll
        for (int i = tid; i < DD * (NC / 4); i += TB) {      // 8192 float4s
            int row = i >> 7, c4 = i & 127;
            float4 t = *(const float4*)&kg[(size_t)row * SS + nb + c4 * 4];
            *(float4*)&KV[row * NC + c4 * 4] = t;
        }
        __syncthreads();

        u64 acc[8][2];
        #pragma unroll
        for (int r = 0; r < 8; r++) { acc[r][0] = 0; acc[r][1] = 0; }

        #pragma unroll 4
        for (int kk = 0; kk < DD; kk++) {
            u64 a0,a1,a2,a3,a4,a5,a6,a7, bx,by;
            const unsigned qk = qa + (unsigned)kk * (QDS * 8u);
            lds_v2u64(qk +  0u, a0, a1);      // rows 0,1 (duplicated pairs) - broadcast
            lds_v2u64(qk + 16u, a2, a3);
            lds_v2u64(qk + 32u, a4, a5);
            lds_v2u64(qk + 48u, a6, a7);
            lds_v2u64(ba + (unsigned)kk * (NC * 4u), bx, by); // 4 cols, 16B vector
            ffma2(acc[0][0], a0, bx); ffma2(acc[0][1], a0, by);
            ffma2(acc[1][0], a1, bx); ffma2(acc[1][1], a1, by);
            ffma2(acc[2][0], a2, bx); ffma2(acc[2][1], a2, by);
            ffma2(acc[3][0], a3, bx); ffma2(acc[3][1], a3, by);
            ffma2(acc[4][0], a4, bx); ffma2(acc[4][1], a4, by);
            ffma2(acc[5][0], a5, bx); ffma2(acc[5][1], a5, by);
            ffma2(acc[6][0], a6, bx); ffma2(acc[6][1], a6, by);
            ffma2(acc[7][0], a7, bx); ffma2(acc[7][1], a7, by);
        }

        // epilogue: *mask*scale + prev; write scores to gmem + smem
        const int gc = nb + colg * 4;
        #pragma unroll
        for (int rr = 0; rr < 8; rr++) {
            const int lr = rowg * 8 + rr;
            const int gr = qbase + lr;
            float2 cA = unpk(acc[rr][0]);
            float2 cB = unpk(acc[rr][1]);
            float4 mk = *(const float4*)&mask[(size_t)gr * SS + gc];
            float4 pv = *(const float4*)&pg[(size_t)gr * SS + gc];
            float4 sc;
            sc.x = fmaf(cA.x * mk.x, scale, pv.x);
            sc.y = fmaf(cA.y * mk.y, scale, pv.y);
            sc.z = fmaf(cB.x * mk.z, scale, pv.z);
            sc.w = fmaf(cB.y * mk.w, scale, pv.w);
            *(float4*)&sg[(size_t)gr * SS + gc] = sc;
            *(float4*)&Ss[lr * SSP + gc] = sc;
        }
    }
    __syncthreads();

    // ================= softmax per row (warp w: rows w, w+8) =================
    // Ss keeps UNNORMALIZED exp; 1/sum stored in Sinv and applied after PV.
    const int warp = tid >> 5, lane = tid & 31;
    #pragma unroll
    for (int r = warp; r < BM; r += 8) {
        float* row = &Ss[r * SSP];
        float m = -3.402823466e38f;
        #pragma unroll 8
        for (int i = lane; i < SS; i += 32) m = fmaxf(m, row[i]);
        #pragma unroll
        for (int o = 16; o > 0; o >>= 1) m = fmaxf(m, __shfl_xor_sync(0xffffffffu, m, o));
        float sum = 0.f;
        #pragma unroll 8
        for (int i = lane; i < SS; i += 32) {
            float e = exp2f((row[i] - m) * 1.4426950408889634f);
            row[i] = e; sum += e;
        }
        #pragma unroll
        for (int o = 16; o > 0; o >>= 1) sum += __shfl_xor_sync(0xffffffffu, sum, o);
        const float inv = 1.0f / sum;
        float* wrow = &wg[(size_t)(qbase + r) * SS];
        #pragma unroll 8
        for (int i = lane; i < SS; i += 32) wrow[i] = row[i] * inv;
        if (lane == 0) Sinv[r] = inv;
    }

    // ================= out = E @ V (split-S over 8 warps, inv folded at end) ====
    // Each warp owns S/8; lane = rowg2(4) x colg2(8); thread tile = rows {rowg2+4j} x 8 cols.
    const int rowg2 = lane >> 3;   // 0..3
    const int colg2 = lane & 7;    // 0..7
    u64 o00=0,o01=0,o02=0,o03=0, o10=0,o11=0,o12=0,o13=0,
        o20=0,o21=0,o22=0,o23=0, o30=0,o31=0,o32=0,o33=0;

    for (int sb = 0; sb < SS; sb += NC) {
        __syncthreads();   // softmax done (first iter) / prior chunk V reads done
        #pragma unroll
        for (int i = tid; i < NC * (DD / 4); i += TB) {      // 8192 float4s
            int row = i >> 4, c4 = i & 15;
            float4 t = *(const float4*)&vg[(size_t)(sb + row) * DD + c4 * 4];
            *(float4*)&KV[row * DD + c4 * 4] = t;
        }
        __syncthreads();

        const int scol0 = sb + warp * (NC / 8);              // this warp's s-slice
        const unsigned wa0 = ss_b + (unsigned)((rowg2 + 0) * SSP + scol0) * 4u;
        const unsigned wa1 = ss_b + (unsigned)((rowg2 + 4) * SSP + scol0) * 4u;
        const unsigned wa2 = ss_b + (unsigned)((rowg2 + 8) * SSP + scol0) * 4u;
        const unsigned wa3 = ss_b + (unsigned)((rowg2 +12) * SSP + scol0) * 4u;
        const unsigned vb  = kv_b + (unsigned)((warp * (NC / 8)) * DD + colg2 * 8) * 4u;

        #pragma unroll 4
        for (int i = 0; i < NC / 8; i++) {                   // 64 s-steps
            u64 b0x, b0y, b1x, b1y;
            const unsigned va = vb + (unsigned)i * (DD * 4u);
            lds_v2u64(va,       b0x, b0y);                   // cols 0..3
            lds_v2u64(va + 16u, b1x, b1y);                   // cols 4..7
            u64 a0 = pack2(lds_f32(wa0 + i * 4u));
            u64 a1 = pack2(lds_f32(wa1 + i * 4u));
            u64 a2 = pack2(lds_f32(wa2 + i * 4u));
            u64 a3 = pack2(lds_f32(wa3 + i * 4u));
            ffma2(o00,a0,b0x); ffma2(o01,a0,b0y); ffma2(o02,a0,b1x); ffma2(o03,a0,b1y);
            ffma2(o10,a1,b0x); ffma2(o11,a1,b0y); ffma2(o12,a1,b1x); ffma2(o13,a1,b1y);
            ffma2(o20,a2,b0x); ffma2(o21,a2,b0y); ffma2(o22,a2,b1x); ffma2(o23,a2,b1y);
            ffma2(o30,a3,b0x); ffma2(o31,a3,b0y); ffma2(o32,a3,b1x); ffma2(o33,a3,b1y);
        }
    }

    // ---- cross-warp reduction of PV partials through smem (reuse KV) ----
    __syncthreads();
    u64* Pu = (u64*)KV;   // [8 warps][16 rows][32 col-pairs] = 4096 u64
    {
        const int base = warp * 512 + colg2 * 4;
        #pragma unroll
        for (int j = 0; j < 4; j++) {
            const int rb = (rowg2 + 4 * j) * 32 + base;
            u64* p = &Pu[rb];
            p[0] = (j==0? o00 : j==1? o10 : j==2? o20 : o30);
            p[1] = (j==0? o01 : j==1? o11 : j==2? o21 : o31);
            p[2] = (j==0? o02 : j==1? o12 : j==2? o22 : o32);
            p[3] = (j==0? o03 : j==1? o13 : j==2? o23 : o33);
        }
    }
    __syncthreads();
    #pragma unroll
    for (int t = tid; t < 512; t += TB) {        // 2 iterations
        const int r = t >> 5, cp = t & 31;
        u64 s64 = Pu[t];
        #pragma unroll
        for (int w2 = 1; w2 < 8; w2++) addf2(s64, Pu[w2 * 512 + t]);
        s64 = mulf2(s64, pack2(Sinv[r]));
        *(u64*)&og[(size_t)(qbase + r) * DD + cp * 2] = s64;
    }
}

extern "C" void kernel_launch(void* const* d_in, const int* in_sizes, int n_in,
                              void* d_out, int out_size) {
    (void)in_sizes; (void)n_in; (void)out_size;
    const float* q     = (const float*)d_in[0];
    const float* k     = (const float*)d_in[1];
    const float* v     = (const float*)d_in[2];
    const float* prev  = (const float*)d_in[3];
    const float* mask  = (const float*)d_in[4];
    const float* scale = (const float*)d_in[5];

    float* out   = (float*)d_out;
    float* out_o = out;                     // [B,H,S,D]
    float* out_w = out + O_ELEMS;           // [B,H,S,S]
    float* out_s = out_w + W_ELEMS;         // [B,H,S,S]

    cudaFuncSetAttribute(attn_fused_v2,
                         cudaFuncAttributeMaxDynamicSharedMemorySize, SMEM_BYTES);

    dim3 grid(SS / BM, NBH);  // (64, 128) = 8192 blocks
    attn_fused_v2<<<grid, TB, SMEM_BYTES>>>(q, k, v, prev, mask, scale,
                                            out_o, out_w, out_s);
}